// round 17
// baseline (speedup 1.0000x reference)
#include <cuda_runtime.h>

// NeRF volume rendering compositing — round 17: micro-margin harvest on the
// R16 body (12.58-12.74us plateau; grid-strided two-rays/warp, 16-lane
// segments, 64-sample rounds, float4 default-cached loads, scan-predicated
// rgb, telescoped weights, no accW). Three combined micro-cuts:
//  1. exp constant fusion: f = exp2f(K*sigma*dist), K = -25*log2(e)
//     (saves one FMUL per sample on the MUFU-feeding chain);
//  2. tau = 2e-4 (measured rel_err coefficient 0.63*tau -> ~1.26e-4,
//     7.9x under the 1e-3 gate; ~1 fewer active rgb lane per segment);
//  3. 64-thread blocks, 16384 blocks, 32/SM — finer dynamic scheduling
//     (monotone gain R12->R13 trend), same 2048 threads/SM.
// Inputs (metadata order):
//   d_in[0]: sigma  [B, S]    float32   (B=65536, S=512)
//   d_in[1]: dists  [B, S]    float32
//   d_in[2]: rgb    [B, S, 3] float32
//   d_in[3]: bg_col [3]       float32
// Output: rgb_map [B, 3] float32
//
//   x = sigma*dists*25; alpha = 1-exp(-x); T = excl cumprod(exp(-x))
//   w = alpha*T; out_c = sum w*sat(rgb) + T_end*bg_c
// Early termination at T < 2e-4: skipped mass telescopes into T_run and is
// composited as background (abs err < tau).

#define EXP2_K    (-36.067376022224085f)   // -25 * log2(e)
#define T_THRESH  2e-4f
#define FULLMASK  0xffffffffu
#define SEGW      16

__global__ __launch_bounds__(64, 32)
void nerf_composite_kernel(const float4* __restrict__ sigma4,
                           const float4* __restrict__ dists4,
                           const float4* __restrict__ rgb4,
                           const float*  __restrict__ bg,
                           float*        __restrict__ out,
                           int B)
{
    const int warp  = (int)((blockIdx.x * (unsigned)blockDim.x + threadIdx.x) >> 5);
    const int lane  = threadIdx.x & 31;
    const int slane = lane & (SEGW - 1);        // lane within 16-lane segment
    const int ray   = warp * 2 + (lane >> 4);   // one ray per half-warp
    if (ray >= B) return;

    float T_run = 1.0f;          // uniform within the segment
    float accR = 0.0f, accG = 0.0f, accB = 0.0f;

    // S = 512 samples = 8 rounds of 64 (4 samples/lane, float4 loads).
    #pragma unroll 1
    for (int k = 0; k < 8; ++k) {
        const int idx = ray * 128 + k * 16 + slane;   // float4 index into sigma/dists
        const float4 sg = sigma4[idx];
        const float4 dt = dists4[idx];

        // Transmittance factors f = exp2(K*sigma*dist) = exp(-25*sigma*dist)
        const float f0 = exp2f(EXP2_K * sg.x * dt.x);
        const float f1 = exp2f(EXP2_K * sg.y * dt.y);
        const float f2 = exp2f(EXP2_K * sg.z * dt.z);
        const float f3 = exp2f(EXP2_K * sg.w * dt.w);

        const float t2 = f0 * f1;        // local prefix products
        const float t3 = t2 * f2;
        const float p  = t3 * f3;        // product of this lane's 4 factors

        // Segment (width-16) inclusive prefix product of p
        float incl = p;
        #pragma unroll
        for (int off = 1; off < SEGW; off <<= 1) {
            const float v = __shfl_up_sync(FULLMASK, incl, off, SEGW);
            if (slane >= off) incl *= v;
        }
        float excl = __shfl_up_sync(FULLMASK, incl, 1, SEGW);
        if (slane == 0) excl = 1.0f;
        const float total = __shfl_sync(FULLMASK, incl, SEGW - 1, SEGW);

        const float Tl = T_run * excl;   // transmittance at this lane's first sample

        // Lanes with negligible remaining transmittance skip rgb traffic.
        if (Tl >= T_THRESH) {
            const int ridx = ray * 384 + k * 48 + slane * 3;   // float4 index into rgb
            const float4 q0 = rgb4[ridx + 0];
            const float4 q1 = rgb4[ridx + 1];
            const float4 q2 = rgb4[ridx + 2];

            // Scaled transmittance ladder: a_i = Tl * prefix_i
            const float a1 = Tl * f0;
            const float a2 = Tl * t2;
            const float a3 = Tl * t3;
            const float a4 = Tl * p;
            const float w0 = Tl - a1;     // w_i * Tl, telescoped
            const float w1 = a1 - a2;
            const float w2 = a2 - a3;
            const float w3 = a3 - a4;

            accR += w0 * __saturatef(q0.x) + w1 * __saturatef(q0.w)
                  + w2 * __saturatef(q1.z) + w3 * __saturatef(q2.y);
            accG += w0 * __saturatef(q0.y) + w1 * __saturatef(q1.x)
                  + w2 * __saturatef(q1.w) + w3 * __saturatef(q2.z);
            accB += w0 * __saturatef(q0.z) + w1 * __saturatef(q1.y)
                  + w2 * __saturatef(q2.x) + w3 * __saturatef(q2.w);
        }

        T_run *= total;                          // stays segment-uniform
        const bool done = (T_run < T_THRESH);
        if (__all_sync(FULLMASK, done)) break;   // warp-uniform early exit
    }

    // Segment (width-16) reduction of the 3 color accumulators.
    #pragma unroll
    for (int off = SEGW / 2; off >= 1; off >>= 1) {
        accR += __shfl_down_sync(FULLMASK, accR, off, SEGW);
        accG += __shfl_down_sync(FULLMASK, accG, off, SEGW);
        accB += __shfl_down_sync(FULLMASK, accB, off, SEGW);
    }

    if (slane == 0) {
        // 1 - sum(processed w) telescopes exactly to T_run; sub-threshold
        // weight mass stays inside T_run and composites as background.
        const float rem = T_run;
        out[ray * 3 + 0] = accR + rem * __ldg(&bg[0]);
        out[ray * 3 + 1] = accG + rem * __ldg(&bg[1]);
        out[ray * 3 + 2] = accB + rem * __ldg(&bg[2]);
    }
}

extern "C" void kernel_launch(void* const* d_in, const int* in_sizes, int n_in,
                              void* d_out, int out_size)
{
    const float4* sigma4 = (const float4*)d_in[0];
    const float4* dists4 = (const float4*)d_in[1];
    const float4* rgb4   = (const float4*)d_in[2];
    const float*  bg     = (const float*) d_in[3];
    float*        out    = (float*)d_out;

    const int B = in_sizes[0] / 512;           // 65536 rays
    const int threads = 64;                     // 2 warps/block -> 4 rays/block
    const int blocks  = (B + 3) / 4;            // 16384 blocks

    nerf_composite_kernel<<<blocks, threads>>>(sigma4, dists4, rgb4, bg, out, B);
}